// round 6
// baseline (speedup 1.0000x reference)
#include <cuda_runtime.h>
#include <math.h>

// Problem constants
#define BATCH 4
#define CIN   256
#define NTOK  2304          // 48*48
#define NH    8
#define HD    64            // dk = dv = 64
#define QKVW  512           // NH*HD

// ---------------------------------------------------------------------------
// Scratch (device globals; no runtime allocation). 16B-aligned for float4.
// layout q/k/v: [b][h][n][d]   (fp32)
// layout ot:    [b][h*64+d][n] (fp32) -- transposed for coalesced out-proj
// ---------------------------------------------------------------------------
__device__ __align__(16) float g_q [BATCH * NH * NTOK * HD];
__device__ __align__(16) float g_k [BATCH * NH * NTOK * HD];
__device__ __align__(16) float g_v [BATCH * NH * NTOK * HD];
__device__ __align__(16) float g_ot[BATCH * QKVW * NTOK];

// ===========================================================================
// Kernel 1: fused QKV projection.
// C[b][m][j] = sum_k x[b][k][m] * W[k][j],  j in [0,1536) selects Wq/Wk/Wv.
// Tile: BM=128 (tokens) x BN=64 (out cols) x BK=16. 128 thr, 8x8 microtile.
// ===========================================================================
#define P1_BM 128
#define P1_BN 64
#define P1_BK 16

__global__ __launch_bounds__(128) void qkv_kernel(
    const float* __restrict__ x,
    const float* __restrict__ Wq,
    const float* __restrict__ Wk,
    const float* __restrict__ Wv)
{
    __shared__ float a_s[P1_BK][P1_BM];
    __shared__ float b_s[P1_BK][P1_BN];

    const int b   = blockIdx.z;
    const int m0  = blockIdx.x * P1_BM;
    const int j0t = blockIdx.y * P1_BN;           // 0..1535
    const int w   = j0t / QKVW;                   // 0=q 1=k 2=v
    const int j0  = j0t % QKVW;
    const float* __restrict__ Wsel = (w == 0) ? Wq : (w == 1) ? Wk : Wv;
    float* __restrict__ dsel = (w == 0) ? g_q : (w == 1) ? g_k : g_v;

    const int tid = threadIdx.x;
    const int tr  = tid >> 3;   // 0..15  (token rows: tr + 16*i)
    const int tc  = tid & 7;    // 0..7   (out cols:  tc + 8*j)

    float acc[8][8];
    #pragma unroll
    for (int i = 0; i < 8; i++)
        #pragma unroll
        for (int j = 0; j < 8; j++) acc[i][j] = 0.f;

    for (int k0 = 0; k0 < CIN; k0 += P1_BK) {
        // a tile: 16x128 floats = 512 float4 -> 4 per thread
        #pragma unroll
        for (int t = 0; t < 4; ++t) {
            int idx = tid + t * 128;
            int kk = idx >> 5, m4 = idx & 31;
            float4 va = *(const float4*)&x[((size_t)b * CIN + k0 + kk) * NTOK + m0 + m4 * 4];
            *(float4*)&a_s[kk][m4 * 4] = va;
        }
        // b tile: 16x64 floats = 256 float4 -> 2 per thread
        #pragma unroll
        for (int t = 0; t < 2; ++t) {
            int idx = tid + t * 128;
            int kk = idx >> 4, j4 = idx & 15;
            float4 vb = *(const float4*)&Wsel[(size_t)(k0 + kk) * QKVW + j0 + j4 * 4];
            *(float4*)&b_s[kk][j4 * 4] = vb;
        }
        __syncthreads();
        #pragma unroll
        for (int kk = 0; kk < P1_BK; ++kk) {
            float a[8], bb[8];
            #pragma unroll
            for (int i = 0; i < 8; i++) a[i] = a_s[kk][tr + 16 * i];
            #pragma unroll
            for (int j = 0; j < 8; j++) bb[j] = b_s[kk][tc + 8 * j];
            #pragma unroll
            for (int i = 0; i < 8; i++)
                #pragma unroll
                for (int j = 0; j < 8; j++) acc[i][j] += a[i] * bb[j];
        }
        __syncthreads();
    }

    // store to [b][h][n][d]
    #pragma unroll
    for (int i = 0; i < 8; i++) {
        int n = m0 + tr + 16 * i;
        #pragma unroll
        for (int j = 0; j < 8; j++) {
            int jg = j0 + tc + 8 * j;     // 0..511
            int h  = jg >> 6, d = jg & 63;
            dsel[(((size_t)b * NH + h) * NTOK + n) * HD + d] = acc[i][j];
        }
    }
}

// ===========================================================================
// Kernel 2: flash attention (fp32, online softmax), software-pipelined K/V
// with DISJOINT prefetch lifetimes to stay spill-free:
//   - next-K loads issued before QK^T (hidden by 64-step FFMA loop; s live)
//   - next-V loads issued before PV   (hidden by 64-step FFMA loop; s dead)
// Per CTA: 128 query rows x full KV sweep in 64-row tiles, one (b,h).
// 128 threads, 8x8 microtiles.
// A_LD = 68 floats (272B = 17*16) -> float4-aligned rows AND coefficient
// 68 mod 32 = 4 keeps all inner-loop LDS broadcast/conflict-free.
// Quirk: softmax scale applied AFTER softmax -> final O *= 0.125/l.
// ===========================================================================
#define A_BM 128
#define A_BN 64
#define A_LD 68   // padded row stride: multiple of 4 (float4-safe), !=64 (banks)

// dynamic smem layout (floats):
//   q_s [A_BM][A_LD]   p_s [A_BM][A_LD]   k_s [A_BN][A_LD]   v_s [A_BN][A_LD]
#define ATTN_SMEM_FLOATS ((A_BM + A_BM + A_BN + A_BN) * A_LD)
#define ATTN_SMEM_BYTES  (ATTN_SMEM_FLOATS * 4)

__global__ __launch_bounds__(128) void attn_kernel()
{
    extern __shared__ float smem[];
    float* q_s = smem;                               // [A_BM][A_LD]
    float* p_s = q_s + A_BM * A_LD;                  // [A_BM][A_LD]
    float* k_s = p_s + A_BM * A_LD;                  // [A_BN][A_LD]
    float* v_s = k_s + A_BN * A_LD;                  // [A_BN][A_LD]

    const int b  = blockIdx.z;
    const int h  = blockIdx.y;
    const int m0 = blockIdx.x * A_BM;

    const size_t base = ((size_t)b * NH + h) * NTOK * HD;
    const float* __restrict__ qb = g_q + base;
    const float* __restrict__ kb = g_k + base;
    const float* __restrict__ vb = g_v + base;

    const int tid = threadIdx.x;
    const int tr  = tid >> 3;   // 0..15 (rows: tr + 16*i)
    const int tc  = tid & 7;    // 0..7  (cols: tc + 8*j)

    // K/V staging: 64 rows x 16 float4/row = 1024 float4; 128 thr -> 8 each.
    const int ldrow = tid >> 4;        // 0..7 : rows ldrow + 8*t
    const int ldc4  = tid & 15;        // 0..15: float4 column

    // load Q tile [128][64] (float4)
    #pragma unroll
    for (int t = 0; t < 16; ++t) {     // 128*64/4 = 2048 f4 / 128 thr = 16
        int f = tid + t * 128;
        int m = f >> 4, d4 = f & 15;
        float4 v = *(const float4*)&qb[(size_t)(m0 + m) * HD + d4 * 4];
        *(float4*)&q_s[m * A_LD + d4 * 4] = v;
    }

    float o[8][8];
    float mrow[8], lrow[8];
    #pragma unroll
    for (int i = 0; i < 8; i++) {
        mrow[i] = -INFINITY; lrow[i] = 0.f;
        #pragma unroll
        for (int j = 0; j < 8; j++) o[i][j] = 0.f;
    }

    // --- prefetch tile 0 K and V into registers
    float4 kreg[8], vreg[8];
    #pragma unroll
    for (int t = 0; t < 8; ++t) {
        int r = ldrow + 8 * t;
        kreg[t] = *(const float4*)&kb[(size_t)r * HD + ldc4 * 4];
        vreg[t] = *(const float4*)&vb[(size_t)r * HD + ldc4 * 4];
    }

    const int NTILES = NTOK / A_BN;   // 36
    for (int tile = 0; tile < NTILES; ++tile) {
        __syncthreads();   // prior tile's k/v/p reads done
        // commit prefetched registers to smem (kreg/vreg die here)
        #pragma unroll
        for (int t = 0; t < 8; ++t) {
            int r = ldrow + 8 * t;
            *(float4*)&k_s[r * A_LD + ldc4 * 4] = kreg[t];
            *(float4*)&v_s[r * A_LD + ldc4 * 4] = vreg[t];
        }
        __syncthreads();

        const int n0n = (tile + 1) * A_BN;
        const bool more = (tile + 1 < NTILES);

        // issue next-tile K loads NOW (latency hidden by QK^T below)
        if (more) {
            #pragma unroll
            for (int t = 0; t < 8; ++t)
                kreg[t] = *(const float4*)&kb[(size_t)(n0n + ldrow + 8 * t) * HD + ldc4 * 4];
        }

        // S = Q K^T  (raw, no pre-scale — faithful to reference)
        float s[8][8];
        #pragma unroll
        for (int i = 0; i < 8; i++)
            #pragma unroll
            for (int j = 0; j < 8; j++) s[i][j] = 0.f;

        #pragma unroll 4
        for (int d = 0; d < HD; ++d) {
            float a[8], bb[8];
            #pragma unroll
            for (int i = 0; i < 8; i++) a[i] = q_s[(tr + 16 * i) * A_LD + d];
            #pragma unroll
            for (int j = 0; j < 8; j++) bb[j] = k_s[(tc + 8 * j) * A_LD + d];
            #pragma unroll
            for (int i = 0; i < 8; i++)
                #pragma unroll
                for (int j = 0; j < 8; j++) s[i][j] += a[i] * bb[j];
        }

        // online softmax update (rows split across 8 lanes: xor 1,2,4)
        #pragma unroll
        for (int i = 0; i < 8; i++) {
            float mx = s[i][0];
            #pragma unroll
            for (int j = 1; j < 8; j++) mx = fmaxf(mx, s[i][j]);
            mx = fmaxf(mx, __shfl_xor_sync(0xffffffffu, mx, 1));
            mx = fmaxf(mx, __shfl_xor_sync(0xffffffffu, mx, 2));
            mx = fmaxf(mx, __shfl_xor_sync(0xffffffffu, mx, 4));
            float mnew  = fmaxf(mrow[i], mx);
            float alpha = __expf(mrow[i] - mnew);
            mrow[i] = mnew;
            float rs = 0.f;
            #pragma unroll
            for (int j = 0; j < 8; j++) {
                s[i][j] = __expf(s[i][j] - mnew);
                rs += s[i][j];
            }
            rs += __shfl_xor_sync(0xffffffffu, rs, 1);
            rs += __shfl_xor_sync(0xffffffffu, rs, 2);
            rs += __shfl_xor_sync(0xffffffffu, rs, 4);
            lrow[i] = lrow[i] * alpha + rs;
            #pragma unroll
            for (int j = 0; j < 8; j++) o[i][j] *= alpha;
        }

        // stage P in smem for the PV GEMM (s dies after this)
        #pragma unroll
        for (int i = 0; i < 8; i++)
            #pragma unroll
            for (int j = 0; j < 8; j++)
                p_s[(tr + 16 * i) * A_LD + tc + 8 * j] = s[i][j];
        __syncthreads();

        // issue next-tile V loads NOW (latency hidden by PV below; s is dead)
        if (more) {
            #pragma unroll
            for (int t = 0; t < 8; ++t)
                vreg[t] = *(const float4*)&vb[(size_t)(n0n + ldrow + 8 * t) * HD + ldc4 * 4];
        }

        // O += P @ V
        #pragma unroll 4
        for (int j2 = 0; j2 < A_BN; ++j2) {
            float a[8], bb[8];
            #pragma unroll
            for (int i = 0; i < 8; i++) a[i] = p_s[(tr + 16 * i) * A_LD + j2];
            #pragma unroll
            for (int j = 0; j < 8; j++) bb[j] = v_s[j2 * A_LD + tc + 8 * j];
            #pragma unroll
            for (int i = 0; i < 8; i++)
                #pragma unroll
                for (int j = 0; j < 8; j++) o[i][j] += a[i] * bb[j];
        }
    }

    // epilogue: /l, post-softmax scale 1/sqrt(64)=0.125, write [b][h*64+d][n]
    #pragma unroll
    for (int i = 0; i < 8; i++) {
        float inv = 0.125f / lrow[i];
        int n = m0 + tr + 16 * i;
        #pragma unroll
        for (int j = 0; j < 8; j++) {
            int d = tc + 8 * j;
            g_ot[((size_t)b * QKVW + h * HD + d) * NTOK + n] = o[i][j] * inv;
        }
    }
}

// ===========================================================================
// Kernel 3: output projection (transposed form for coalescing).
// out[b][c][n] = sum_j Wo[j][c] * ot[b][j][n]
// M=256 (c), N=2304 (n), K=512. Tile 64x128x16, 128 thr, 8x8 microtile.
// ===========================================================================
#define P3_BM 64
#define P3_BN 128
#define P3_BK 16

__global__ __launch_bounds__(128) void oproj_kernel(
    const float* __restrict__ Wo, float* __restrict__ out)
{
    __shared__ float a_s[P3_BK][P3_BM];   // Wo[k][c]
    __shared__ float b_s[P3_BK][P3_BN];   // ot[k][n]

    const int b  = blockIdx.z;
    const int c0 = blockIdx.x * P3_BM;
    const int n0 = blockIdx.y * P3_BN;

    const int tid = threadIdx.x;
    const int tr  = tid >> 4;   // 0..7  (c rows: tr + 8*i)
    const int tc  = tid & 15;   // 0..15 (n cols: tc + 16*j)

    float acc[8][8];
    #pragma unroll
    for (int i = 0; i < 8; i++)
        #pragma unroll
        for (int j = 0; j < 8; j++) acc[i][j] = 0.f;

    for (int k0 = 0; k0 < QKVW; k0 += P3_BK) {
        // a: 16x64 = 256 f4 -> 2 per thread
        #pragma unroll
        for (int t = 0; t < 2; ++t) {
            int f = tid + t * 128;
            int kk = f >> 4, c4 = f & 15;
            float4 v = *(const float4*)&Wo[(size_t)(k0 + kk) * CIN + c0 + c4 * 4];
            *(float4*)&a_s[kk][c4 * 4] = v;
        }
        // b: 16x128 = 512 f4 -> 4 per thread
        #pragma unroll
        for (int t = 0; t < 4; ++t) {
            int f = tid + t * 128;
            int kk = f >> 5, n4 = f & 31;
            float4 v = *(const float4*)&g_ot[((size_t)b * QKVW + k0 + kk) * NTOK + n0 + n4 * 4];
            *(float4*)&b_s[kk][n4 * 4] = v;
        }
        __syncthreads();
        #pragma unroll
        for (int kk = 0; kk < P3_BK; ++kk) {
            float a[8], bb[8];
            #pragma unroll
            for (int i = 0; i < 8; i++) a[i] = a_s[kk][tr + 8 * i];
            #pragma unroll
            for (int j = 0; j < 8; j++) bb[j] = b_s[kk][tc + 16 * j];
            #pragma unroll
            for (int i = 0; i < 8; i++)
                #pragma unroll
                for (int j = 0; j < 8; j++) acc[i][j] += a[i] * bb[j];
        }
        __syncthreads();
    }

    #pragma unroll
    for (int i = 0; i < 8; i++) {
        int c = c0 + tr + 8 * i;
        #pragma unroll
        for (int j = 0; j < 8; j++) {
            int n = n0 + tc + 16 * j;
            out[((size_t)b * CIN + c) * NTOK + n] = acc[i][j];
        }
    }
}

// ===========================================================================
extern "C" void kernel_launch(void* const* d_in, const int* in_sizes, int n_in,
                              void* d_out, int out_size)
{
    const float* x  = (const float*)d_in[0];
    const float* Wq = (const float*)d_in[1];
    const float* Wk = (const float*)d_in[2];
    const float* Wv = (const float*)d_in[3];
    const float* Wo = (const float*)d_in[4];
    float* out = (float*)d_out;

    // opt-in >48KB dynamic smem for the attention kernel (idempotent, non-stream)
    cudaFuncSetAttribute(attn_kernel,
                         cudaFuncAttributeMaxDynamicSharedMemorySize,
                         ATTN_SMEM_BYTES);

    // 1) QKV projection: grid (18 m-tiles, 24 j-tiles, 4 batches)
    qkv_kernel<<<dim3(NTOK / P1_BM, (3 * QKVW) / P1_BN, BATCH), 128>>>(
        x, Wq, Wk, Wv);

    // 2) flash attention: grid (18 q-tiles, 8 heads, 4 batches)
    attn_kernel<<<dim3(NTOK / A_BM, NH, BATCH), 128, ATTN_SMEM_BYTES>>>();

    // 3) output projection: grid (4 c-tiles, 18 n-tiles, 4 batches)
    oproj_kernel<<<dim3(CIN / P3_BM, NTOK / P3_BN, BATCH), 128>>>(Wo, out);
}

// round 10
// speedup vs baseline: 2.1142x; 2.1142x over previous
#include <cuda_runtime.h>
#include <math.h>
#include <stdint.h>

// Problem constants
#define BATCH 4
#define CIN   256
#define NTOK  2304          // 48*48
#define NH    8
#define HD    64            // dk = dv = 64
#define QKVW  512           // NH*HD

// ---------------------------------------------------------------------------
// Scratch (device globals; no runtime allocation). 16B-aligned for float4.
// ---------------------------------------------------------------------------
__device__ __align__(16) float g_q [BATCH * NH * NTOK * HD];
__device__ __align__(16) float g_k [BATCH * NH * NTOK * HD];
__device__ __align__(16) float g_v [BATCH * NH * NTOK * HD];
__device__ __align__(16) float g_ot[BATCH * QKVW * NTOK];

// ===========================================================================
// Kernel 1: fused QKV projection (unchanged — measured 227us, fma-bound).
// ===========================================================================
#define P1_BM 128
#define P1_BN 64
#define P1_BK 16

__global__ __launch_bounds__(128) void qkv_kernel(
    const float* __restrict__ x,
    const float* __restrict__ Wq,
    const float* __restrict__ Wk,
    const float* __restrict__ Wv)
{
    __shared__ float a_s[P1_BK][P1_BM];
    __shared__ float b_s[P1_BK][P1_BN];

    const int b   = blockIdx.z;
    const int m0  = blockIdx.x * P1_BM;
    const int j0t = blockIdx.y * P1_BN;
    const int w   = j0t / QKVW;
    const int j0  = j0t % QKVW;
    const float* __restrict__ Wsel = (w == 0) ? Wq : (w == 1) ? Wk : Wv;
    float* __restrict__ dsel = (w == 0) ? g_q : (w == 1) ? g_k : g_v;

    const int tid = threadIdx.x;
    const int tr  = tid >> 3;
    const int tc  = tid & 7;

    float acc[8][8];
    #pragma unroll
    for (int i = 0; i < 8; i++)
        #pragma unroll
        for (int j = 0; j < 8; j++) acc[i][j] = 0.f;

    for (int k0 = 0; k0 < CIN; k0 += P1_BK) {
        #pragma unroll
        for (int t = 0; t < 4; ++t) {
            int idx = tid + t * 128;
            int kk = idx >> 5, m4 = idx & 31;
            float4 va = *(const float4*)&x[((size_t)b * CIN + k0 + kk) * NTOK + m0 + m4 * 4];
            *(float4*)&a_s[kk][m4 * 4] = va;
        }
        #pragma unroll
        for (int t = 0; t < 2; ++t) {
            int idx = tid + t * 128;
            int kk = idx >> 4, j4 = idx & 15;
            float4 vb = *(const float4*)&Wsel[(size_t)(k0 + kk) * QKVW + j0 + j4 * 4];
            *(float4*)&b_s[kk][j4 * 4] = vb;
        }
        __syncthreads();
        #pragma unroll
        for (int kk = 0; kk < P1_BK; ++kk) {
            float a[8], bb[8];
            #pragma unroll
            for (int i = 0; i < 8; i++) a[i] = a_s[kk][tr + 16 * i];
            #pragma unroll
            for (int j = 0; j < 8; j++) bb[j] = b_s[kk][tc + 8 * j];
            #pragma unroll
            for (int i = 0; i < 8; i++)
                #pragma unroll
                for (int j = 0; j < 8; j++) acc[i][j] += a[i] * bb[j];
        }
        __syncthreads();
    }

    #pragma unroll
    for (int i = 0; i < 8; i++) {
        int n = m0 + tr + 16 * i;
        #pragma unroll
        for (int j = 0; j < 8; j++) {
            int jg = j0 + tc + 8 * j;
            int h  = jg >> 6, d = jg & 63;
            dsel[(((size_t)b * NH + h) * NTOK + n) * HD + d] = acc[i][j];
        }
    }
}

// ===========================================================================
// Kernel 2: flash attention with tf32 mma.sync (m16n8k8).
//   S = QK^T and O += PV on tensor cores; fp32 online softmax between them.
//   8 warps (256 thr); warp w owns 16 q-rows (one m16 tile).
//   Fragment maps (PTX m16n8k8 tf32, g=lane>>2, t=lane&3):
//     A: a0=A[g][t] a1=A[g+8][t] a2=A[g][t+4] a3=A[g+8][t+4]
//     B: b0=B[t][g] b1=B[t+4][g]
//     C: c0=C[g][2t] c1=C[g][2t+1] c2=C[g+8][2t] c3=C[g+8][2t+1]
//   V stays [key][d]: PV B-frag b0 = V[8kt+t][8nt+g] -- no transpose needed.
//   P rows are warp-private in p_s -> no barrier between softmax and PV.
//   Bank pads: LDQ/LDK/LDP=68 (=4 mod 32: 4g+t distinct), LDV=72 (8t+g distinct).
//   Quirk: softmax scale applied AFTER softmax -> final O *= 0.125/l.
// ===========================================================================
#define A_BM 128
#define A_BN 64
#define LDQ 68
#define LDP 68
#define LDK 68
#define LDV 72

#define ATTN_SMEM_FLOATS (A_BM*LDQ + A_BM*LDP + A_BN*LDK + A_BN*LDV)
#define ATTN_SMEM_BYTES  (ATTN_SMEM_FLOATS * 4)

__device__ __forceinline__ uint32_t f2tf32(float f) {
    uint32_t r;
    asm("cvt.rna.tf32.f32 %0, %1;" : "=r"(r) : "f"(f));
    return r;
}

__device__ __forceinline__ void mma_tf32(float c[4],
    uint32_t a0, uint32_t a1, uint32_t a2, uint32_t a3,
    uint32_t b0, uint32_t b1)
{
    asm volatile(
        "mma.sync.aligned.m16n8k8.row.col.f32.tf32.tf32.f32 "
        "{%0,%1,%2,%3}, {%4,%5,%6,%7}, {%8,%9}, {%0,%1,%2,%3};"
        : "+f"(c[0]), "+f"(c[1]), "+f"(c[2]), "+f"(c[3])
        : "r"(a0), "r"(a1), "r"(a2), "r"(a3), "r"(b0), "r"(b1));
}

__global__ __launch_bounds__(256, 1) void attn_kernel()
{
    extern __shared__ float smem[];
    float* q_s = smem;                     // [128][LDQ] tf32 bits
    float* p_s = q_s + A_BM * LDQ;         // [128][LDP] tf32 bits
    float* k_s = p_s + A_BM * LDP;         // [64][LDK]  tf32 bits
    float* v_s = k_s + A_BN * LDK;         // [64][LDV]  tf32 bits
    uint32_t* q_u = (uint32_t*)q_s;
    uint32_t* p_u = (uint32_t*)p_s;
    uint32_t* k_u = (uint32_t*)k_s;
    uint32_t* v_u = (uint32_t*)v_s;

    const int b  = blockIdx.z;
    const int h  = blockIdx.y;
    const int m0 = blockIdx.x * A_BM;

    const size_t base = ((size_t)b * NH + h) * NTOK * HD;
    const float* __restrict__ qb = g_q + base;
    const float* __restrict__ kb = g_k + base;
    const float* __restrict__ vb = g_v + base;

    const int tid  = threadIdx.x;
    const int w    = tid >> 5;
    const int lane = tid & 31;
    const int g    = lane >> 2;     // groupID 0..7
    const int t    = lane & 3;      // threadID_in_group 0..3
    const int rA   = 16 * w + g;    // this thread's upper row (lower = rA+8)

    // ---- stage Q (convert to tf32): 128x64 = 2048 f4, 256 thr -> 8 each
    #pragma unroll
    for (int tt = 0; tt < 8; ++tt) {
        int f = tid + tt * 256;
        int m = f >> 4, d4 = f & 15;
        float4 v = *(const float4*)&qb[(size_t)(m0 + m) * HD + d4 * 4];
        uint32_t* dst = &q_u[m * LDQ + d4 * 4];
        dst[0] = f2tf32(v.x); dst[1] = f2tf32(v.y);
        dst[2] = f2tf32(v.z); dst[3] = f2tf32(v.w);
    }

    // ---- prefetch K/V tile 0 (raw fp32; cvt at commit)
    // 64x64 = 1024 f4 per matrix, 256 thr -> 4 each; f = tid+256t: r=f>>4, c4=f&15
    const int ldr = tid >> 4;      // 0..15
    const int ldc = tid & 15;      // 0..15
    float4 kreg[4], vreg[4];
    #pragma unroll
    for (int tt = 0; tt < 4; ++tt) {
        int r = ldr + 16 * tt;
        kreg[tt] = *(const float4*)&kb[(size_t)r * HD + ldc * 4];
        vreg[tt] = *(const float4*)&vb[(size_t)r * HD + ldc * 4];
    }

    // ---- accumulators / softmax state
    float o[8][4];
    #pragma unroll
    for (int nt = 0; nt < 8; nt++)
        #pragma unroll
        for (int c = 0; c < 4; c++) o[nt][c] = 0.f;
    float m0_ = -INFINITY, m1_ = -INFINITY, l0_ = 0.f, l1_ = 0.f;

    const int NTILES = NTOK / A_BN;   // 36
    for (int tile = 0; tile < NTILES; ++tile) {
        __syncthreads();   // prior tile's k_s/v_s reads complete
        // commit prefetch (cvt -> tf32)
        #pragma unroll
        for (int tt = 0; tt < 4; ++tt) {
            int r = ldr + 16 * tt;
            uint32_t* dk = &k_u[r * LDK + ldc * 4];
            dk[0] = f2tf32(kreg[tt].x); dk[1] = f2tf32(kreg[tt].y);
            dk[2] = f2tf32(kreg[tt].z); dk[3] = f2tf32(kreg[tt].w);
            uint32_t* dv = &v_u[r * LDV + ldc * 4];
            dv[0] = f2tf32(vreg[tt].x); dv[1] = f2tf32(vreg[tt].y);
            dv[2] = f2tf32(vreg[tt].z); dv[3] = f2tf32(vreg[tt].w);
        }
        __syncthreads();

        const int n0n = (tile + 1) * A_BN;
        const bool more = (tile + 1 < NTILES);

        // prefetch next K (hidden by QK^T mma below)
        if (more) {
            #pragma unroll
            for (int tt = 0; tt < 4; ++tt)
                kreg[tt] = *(const float4*)&kb[(size_t)(n0n + ldr + 16 * tt) * HD + ldc * 4];
        }

        // ---- S = Q K^T via tf32 mma: 8 k-steps x 8 n-tiles
        float s[8][4];
        #pragma unroll
        for (int nt = 0; nt < 8; nt++)
            #pragma unroll
            for (int c = 0; c < 4; c++) s[nt][c] = 0.f;

        #pragma unroll
        for (int ks = 0; ks < 8; ++ks) {
            int qa = rA * LDQ + 8 * ks + t;
            uint32_t a0 = q_u[qa];
            uint32_t a1 = q_u[qa + 8 * LDQ];
            uint32_t a2 = q_u[qa + 4];
            uint32_t a3 = q_u[qa + 8 * LDQ + 4];
            #pragma unroll
            for (int nt = 0; nt < 8; ++nt) {
                int kaddr = (8 * nt + g) * LDK + 8 * ks + t;
                uint32_t b0 = k_u[kaddr];
                uint32_t b1 = k_u[kaddr + 4];
                mma_tf32(s[nt], a0, a1, a2, a3, b0, b1);
            }
        }

        // ---- online softmax (rows rA and rA+8; quad = lanes sharing g)
        float mx0 = -INFINITY, mx1 = -INFINITY;
        #pragma unroll
        for (int nt = 0; nt < 8; nt++) {
            mx0 = fmaxf(mx0, fmaxf(s[nt][0], s[nt][1]));
            mx1 = fmaxf(mx1, fmaxf(s[nt][2], s[nt][3]));
        }
        mx0 = fmaxf(mx0, __shfl_xor_sync(0xffffffffu, mx0, 1));
        mx0 = fmaxf(mx0, __shfl_xor_sync(0xffffffffu, mx0, 2));
        mx1 = fmaxf(mx1, __shfl_xor_sync(0xffffffffu, mx1, 1));
        mx1 = fmaxf(mx1, __shfl_xor_sync(0xffffffffu, mx1, 2));

        float mnew0 = fmaxf(m0_, mx0), mnew1 = fmaxf(m1_, mx1);
        float alpha0 = __expf(m0_ - mnew0), alpha1 = __expf(m1_ - mnew1);
        m0_ = mnew0; m1_ = mnew1;

        float rs0 = 0.f, rs1 = 0.f;
        #pragma unroll
        for (int nt = 0; nt < 8; nt++) {
            s[nt][0] = __expf(s[nt][0] - mnew0);
            s[nt][1] = __expf(s[nt][1] - mnew0);
            s[nt][2] = __expf(s[nt][2] - mnew1);
            s[nt][3] = __expf(s[nt][3] - mnew1);
            rs0 += s[nt][0] + s[nt][1];
            rs1 += s[nt][2] + s[nt][3];
        }
        rs0 += __shfl_xor_sync(0xffffffffu, rs0, 1);
        rs0 += __shfl_xor_sync(0xffffffffu, rs0, 2);
        rs1 += __shfl_xor_sync(0xffffffffu, rs1, 1);
        rs1 += __shfl_xor_sync(0xffffffffu, rs1, 2);
        l0_ = l0_ * alpha0 + rs0;
        l1_ = l1_ * alpha1 + rs1;

        #pragma unroll
        for (int nt = 0; nt < 8; nt++) {
            o[nt][0] *= alpha0; o[nt][1] *= alpha0;
            o[nt][2] *= alpha1; o[nt][3] *= alpha1;
        }

        // ---- store P (tf32) to warp-private p_s rows; no CTA barrier needed
        #pragma unroll
        for (int nt = 0; nt < 8; nt++) {
            uint32_t* d0 = &p_u[rA * LDP + 8 * nt + 2 * t];
            d0[0] = f2tf32(s[nt][0]); d0[1] = f2tf32(s[nt][1]);
            uint32_t* d1 = &p_u[(rA + 8) * LDP + 8 * nt + 2 * t];
            d1[0] = f2tf32(s[nt][2]); d1[1] = f2tf32(s[nt][3]);
        }

        // prefetch next V (hidden by PV mma below; s regs now dead)
        if (more) {
            #pragma unroll
            for (int tt = 0; tt < 4; ++tt)
                vreg[tt] = *(const float4*)&vb[(size_t)(n0n + ldr + 16 * tt) * HD + ldc * 4];
        }

        // ---- O += P V via tf32 mma: 8 k-tiles x 8 n-tiles (d)
        #pragma unroll
        for (int kt = 0; kt < 8; ++kt) {
            int pa = rA * LDP + 8 * kt + t;
            uint32_t a0 = p_u[pa];
            uint32_t a1 = p_u[pa + 8 * LDP];
            uint32_t a2 = p_u[pa + 4];
            uint32_t a3 = p_u[pa + 8 * LDP + 4];
            #pragma unroll
            for (int nt = 0; nt < 8; ++nt) {
                int vaddr = (8 * kt + t) * LDV + 8 * nt + g;
                uint32_t b0 = v_u[vaddr];
                uint32_t b1 = v_u[vaddr + 4 * LDV];
                mma_tf32(o[nt], a0, a1, a2, a3, b0, b1);
            }
        }
    }

    // ---- epilogue: /l, post-softmax 0.125, write g_ot[b][h*64+d][n]
    const float inv0 = 0.125f / l0_;
    const float inv1 = 0.125f / l1_;
    const int n_up = m0 + rA;
    const int n_lo = m0 + rA + 8;
    const size_t obase = (size_t)b * QKVW + h * HD;
    #pragma unroll
    for (int nt = 0; nt < 8; nt++) {
        int d = 8 * nt + 2 * t;
        g_ot[(obase + d    ) * NTOK + n_up] = o[nt][0] * inv0;
        g_ot[(obase + d + 1) * NTOK + n_up] = o[nt][1] * inv0;
        g_ot[(obase + d    ) * NTOK + n_lo] = o[nt][2] * inv1;
        g_ot[(obase + d + 1) * NTOK + n_lo] = o[nt][3] * inv1;
    }
}

// ===========================================================================
// Kernel 3: output projection (unchanged).
// ===========================================================================
#define P3_BM 64
#define P3_BN 128
#define P3_BK 16

__global__ __launch_bounds__(128) void oproj_kernel(
    const float* __restrict__ Wo, float* __restrict__ out)
{
    __shared__ float a_s[P3_BK][P3_BM];
    __shared__ float b_s[P3_BK][P3_BN];

    const int b  = blockIdx.z;
    const int c0 = blockIdx.x * P3_BM;
    const int n0 = blockIdx.y * P3_BN;

    const int tid = threadIdx.x;
    const int tr  = tid >> 4;
    const int tc  = tid & 15;

    float acc[8][8];
    #pragma unroll
    for (int i = 0; i < 8; i++)
        #pragma unroll
        for (int j = 0; j < 8; j++) acc[i][j] = 0.f;

    for (int k0 = 0; k0 < QKVW; k0 += P3_BK) {
        #pragma unroll
        for (int t = 0; t < 2; ++t) {
            int f = tid + t * 128;
            int kk = f >> 4, c4 = f & 15;
            float4 v = *(const float4*)&Wo[(size_t)(k0 + kk) * CIN + c0 + c4 * 4];
            *(float4*)&a_s[kk][c4 * 4] = v;
        }
        #pragma unroll
        for (int t = 0; t < 4; ++t) {
            int f = tid + t * 128;
            int kk = f >> 5, n4 = f & 31;
            float4 v = *(const float4*)&g_ot[((size_t)b * QKVW + k0 + kk) * NTOK + n0 + n4 * 4];
            *(float4*)&b_s[kk][n4 * 4] = v;
        }
        __syncthreads();
        #pragma unroll
        for (int kk = 0; kk < P3_BK; ++kk) {
            float a[8], bb[8];
            #pragma unroll
            for (int i = 0; i < 8; i++) a[i] = a_s[kk][tr + 8 * i];
            #pragma unroll
            for (int j = 0; j < 8; j++) bb[j] = b_s[kk][tc + 16 * j];
            #pragma unroll
            for (int i = 0; i < 8; i++)
                #pragma unroll
                for (int j = 0; j < 8; j++) acc[i][j] += a[i] * bb[j];
        }
        __syncthreads();
    }

    #pragma unroll
    for (int i = 0; i < 8; i++) {
        int c = c0 + tr + 8 * i;
        #pragma unroll
        for (int j = 0; j < 8; j++) {
            int n = n0 + tc + 16 * j;
            out[((size_t)b * CIN + c) * NTOK + n] = acc[i][j];
        }
    }
}

// ===========================================================================
extern "C" void kernel_launch(void* const* d_in, const int* in_sizes, int n_in,
                              void* d_out, int out_size)
{
    const float* x  = (const float*)d_in[0];
    const float* Wq = (const float*)d_in[1];
    const float* Wk = (const float*)d_in[2];
    const float* Wv = (const float*)d_in[3];
    const float* Wo = (const float*)d_in[4];
    float* out = (float*)d_out;

    cudaFuncSetAttribute(attn_kernel,
                         cudaFuncAttributeMaxDynamicSharedMemorySize,
                         ATTN_SMEM_BYTES);

    qkv_kernel<<<dim3(NTOK / P1_BM, (3 * QKVW) / P1_BN, BATCH), 128>>>(
        x, Wq, Wk, Wv);

    attn_kernel<<<dim3(NTOK / A_BM, NH, BATCH), 256, ATTN_SMEM_BYTES>>>();

    oproj_kernel<<<dim3(CIN / P3_BM, NTOK / P3_BN, BATCH), 128>>>(Wo, out);
}